// round 3
// baseline (speedup 1.0000x reference)
#include <cuda_runtime.h>
#include <cuda_bf16.h>

// text [SEQ=200, BATCH=4096] int32 (row-major text[s*BATCH+b]),
// w [V=50000] f32, bias [1] f32.  out[b] = sum_{unique t in doc b} w[t] + bias.
//
// R3: atomic-free dedup. smem atomics cost ~64 cyc/warp (2 cyc/lane spread) vs
// ~1 cyc/warp for plain LDS/STS; R2 spent most of its time there. Replace with
// a racing plain-byte-store min-marker + barrier repair loop (provably converges
// to exact min tid -> deterministic), plus a rare precise path for hash
// collisions between distinct tokens.

#define SEQ   200
#define BATCH 4096
#define HBITS 13
#define HSIZE (1 << HBITS)   // 8192 byte slots = 8KB

__global__ __launch_bounds__(256, 8)
void MNB_24111946400019_kernel(const int* __restrict__ text,
                               const float* __restrict__ w,
                               const float* __restrict__ bias,
                               float* __restrict__ out)
{
    __shared__ int           toks[SEQ];
    __shared__ unsigned char marker[HSIZE];
    __shared__ int           changed;
    __shared__ float         warp_sums[8];

    const int b   = blockIdx.x;
    const int tid = threadIdx.x;

    // Init marker to 0xFF with 128-bit stores (8192B / 256thr = 2 int4 each).
    // tid values are 0..199, so 0xFF never collides with a real tid.
    {
        int4* m4 = reinterpret_cast<int4*>(marker);
        const int4 ff = make_int4(-1, -1, -1, -1);
        m4[tid]       = ff;
        m4[tid + 256] = ff;
    }
    if (tid == 0) changed = 0;

    int t = 0;
    unsigned h = 0;
    if (tid < SEQ) {
        t = text[tid * BATCH + b];
        toks[tid] = t;
        h = ((unsigned)t * 2654435761u) >> (32 - HBITS);
    }
    __syncthreads();

    // Min-marker via racing plain byte stores + barrier repair rounds.
    // Invariant: every value written in a round is < the round-entry value,
    // so the slot value strictly decreases per round -> exact min, deterministic.
    for (;;) {
        if (tid < SEQ && marker[h] > (unsigned char)tid) {
            marker[h] = (unsigned char)tid;
            changed = 1;                     // idempotent plain store
        }
        __syncthreads();
        int c = changed;
        __syncthreads();
        if (tid == 0) changed = 0;
        if (!c) break;
        __syncthreads();                      // reset visible before next round's writes
    }

    // Decide contribution (exactly one thread per unique token, deterministic).
    float v = 0.0f;
    if (tid < SEQ) {
        const int m = marker[h];              // m = min tid hashing to h; m <= tid
        if (m == tid) {
            v = __ldg(&w[t]);                 // slot winner contributes its token
        } else if (toks[m] != t) {
            // Hash collision with a different token (~2.4/block): precise
            // first-occurrence check via broadcast smem scan.
            int f = 0;
            while (toks[f] != t) ++f;         // terminates: toks[tid] == t
            if (f == tid) v = __ldg(&w[t]);
        }
        // else: duplicate of the slot winner's token -> drop
    }

    // Block reduction (8 warps)
    #pragma unroll
    for (int o = 16; o > 0; o >>= 1)
        v += __shfl_down_sync(0xffffffffu, v, o);
    if ((tid & 31) == 0) warp_sums[tid >> 5] = v;
    __syncthreads();

    if (tid < 32) {
        float s = (tid < 8) ? warp_sums[tid] : 0.0f;
        #pragma unroll
        for (int o = 4; o > 0; o >>= 1)
            s += __shfl_down_sync(0xffffffffu, s, o);
        if (tid == 0) out[b] = s + bias[0];
    }
}

extern "C" void kernel_launch(void* const* d_in, const int* in_sizes, int n_in,
                              void* d_out, int out_size)
{
    const int*   text = (const int*)d_in[0];
    const float* w    = (const float*)d_in[1];
    const float* bias = (const float*)d_in[2];
    float*       out  = (float*)d_out;

    MNB_24111946400019_kernel<<<BATCH, 256>>>(text, w, bias, out);
}

// round 4
// speedup vs baseline: 1.2742x; 1.2742x over previous
#include <cuda_runtime.h>
#include <cuda_bf16.h>

// text [SEQ=200, BATCH=4096] int32 (row-major text[s*BATCH+b]),
// w [V=50000] f32, bias [1] f32.  out[b] = sum_{unique t in doc b} w[t] + bias.
//
// R4: single-round racing dedup. R2's smem atomics cost ~800 cyc/block; R3's
// min-repair loop cost ~900. One plain byte-store race + one barrier + one
// readback is exact for dedup:
//   winner m = some thread that stored to slot h.
//   toks[m]==t : winner contributes, others with same token drop (dupes).
//   toks[m]!=t : different-token hash collision (rare) -> exact
//                first-occurrence scan over the 200-token smem array.
// Winner lane choice is racy but the contributed VALUE w[t] is identical,
// so output varies only in fp reduction order (<< 1e-3 tolerance).

#define SEQ   200
#define BATCH 4096
#define HBITS 13
#define HSIZE (1 << HBITS)   // 8192 byte slots = 8KB

__global__ __launch_bounds__(256, 8)
void MNB_24111946400019_kernel(const int* __restrict__ text,
                               const float* __restrict__ w,
                               const float* __restrict__ bias,
                               float* __restrict__ out)
{
    __shared__ int           toks[SEQ];
    __shared__ unsigned char marker[HSIZE];
    __shared__ float         warp_sums[8];

    const int b   = blockIdx.x;
    const int tid = threadIdx.x;

    // Init marker to 0xFF (sentinel; real tids are 0..199) with int4 stores.
    {
        int4* m4 = reinterpret_cast<int4*>(marker);
        const int4 ff = make_int4(-1, -1, -1, -1);
        m4[tid]       = ff;
        m4[tid + 256] = ff;
    }

    int t = 0;
    unsigned h = 0;
    if (tid < SEQ) {
        t = text[tid * BATCH + b];
        toks[tid] = t;
        h = ((unsigned)t * 2654435761u) >> (32 - HBITS);
    }
    __syncthreads();

    // Single racing store: one of the threads hashing to h wins.
    if (tid < SEQ) marker[h] = (unsigned char)tid;
    __syncthreads();

    float v = 0.0f;
    if (tid < SEQ) {
        const int m = marker[h];              // some racer's tid (byte store: no tearing)
        if (toks[m] == t) {
            if (m == tid) v = __ldg(&w[t]);   // winner contributes; same-token losers drop
        } else {
            // Collision with a *different* token (~2.4/block): exact
            // first-occurrence check via broadcast smem scan.
            int f = 0;
            while (toks[f] != t) ++f;         // terminates: toks[tid] == t
            if (f == tid) v = __ldg(&w[t]);
        }
    }

    // Block reduction (8 warps)
    #pragma unroll
    for (int o = 16; o > 0; o >>= 1)
        v += __shfl_down_sync(0xffffffffu, v, o);
    if ((tid & 31) == 0) warp_sums[tid >> 5] = v;
    __syncthreads();

    if (tid < 32) {
        float s = (tid < 8) ? warp_sums[tid] : 0.0f;
        #pragma unroll
        for (int o = 4; o > 0; o >>= 1)
            s += __shfl_down_sync(0xffffffffu, s, o);
        if (tid == 0) out[b] = s + bias[0];
    }
}

extern "C" void kernel_launch(void* const* d_in, const int* in_sizes, int n_in,
                              void* d_out, int out_size)
{
    const int*   text = (const int*)d_in[0];
    const float* w    = (const float*)d_in[1];
    const float* bias = (const float*)d_in[2];
    float*       out  = (float*)d_out;

    MNB_24111946400019_kernel<<<BATCH, 256>>>(text, w, bias, out);
}

// round 5
// speedup vs baseline: 1.9828x; 1.5560x over previous
#include <cuda_runtime.h>
#include <cuda_bf16.h>

// text [SEQ=200, BATCH=4096] int32 (row-major text[s*BATCH+b]),
// w [V=50000] f32, bias [1] f32.  out[b] = sum_{unique t in doc b} w[t] + bias.
//
// R5: two-level racing dedup. R4's collision fallback (serial 100-iter smem
// scan, ~3000 cyc, hit by ~2.4 threads in EVERY block) is demoted to level 3,
// reached by ~1 block per launch. Level 2 re-races unresolved threads in the
// SAME byte table under a different hash; stale level-1 entries are provably
// never equal to an unresolved thread's token. Barriers separate read/write
// phases so resolution state is consistent per token group (exactly-once).

#define SEQ   200
#define BATCH 4096
#define HBITS 13
#define HSIZE (1 << HBITS)   // 8192 byte slots = 8KB

__global__ __launch_bounds__(256, 8)
void MNB_24111946400019_kernel(const int* __restrict__ text,
                               const float* __restrict__ w,
                               const float* __restrict__ bias,
                               float* __restrict__ out)
{
    __shared__ int           toks[SEQ];
    __shared__ unsigned char marker[HSIZE];
    __shared__ float         warp_sums[8];

    const int b   = blockIdx.x;
    const int tid = threadIdx.x;

    // Init marker to 0xFF (real tids are 0..199) with int4 stores: 8KB.
    {
        int4* m4 = reinterpret_cast<int4*>(marker);
        const int4 ff = make_int4(-1, -1, -1, -1);
        m4[tid]       = ff;
        m4[tid + 256] = ff;
    }

    int t = 0;
    unsigned h1 = 0, h2 = 0;
    if (tid < SEQ) {
        t = text[tid * BATCH + b];
        toks[tid] = t;
        h1 = ((unsigned)t * 2654435761u) >> (32 - HBITS);   // Fibonacci
        h2 = ((unsigned)t * 0x85EBCA77u) >> (32 - HBITS);   // xxhash prime (odd)
    }
    __syncthreads();

    // ── Level 1: racing byte store, one winner per slot ──
    if (tid < SEQ) marker[h1] = (unsigned char)tid;
    __syncthreads();

    int state = 0;                      // 0=drop, 1=contribute, 2=unresolved
    if (tid < SEQ) {
        const int m = marker[h1];       // byte store: no tearing
        if (toks[m] == t) state = (m == tid) ? 1 : 0;   // winner / duplicate
        else              state = 2;    // different-token hash collision (~2.4/blk)
    }
    __syncthreads();                    // level-1 reads complete before level-2 stores

    // ── Level 2: re-race unresolved threads under h2 (same table) ──
    // Stale-entry safety: a stale winner at h2(t) carrying token t would imply
    // h1(t)==h2(t), i.e. this thread resolved at level 1 — contradiction.
    if (state == 2) marker[h2] = (unsigned char)tid;
    __syncthreads();

    float v = 0.0f;
    if (tid < SEQ) {
        if (state == 2) {
            const int m = marker[h2];
            if (toks[m] == t) {
                state = (m == tid) ? 1 : 0;
            } else {
                // ── Level 3 (≈1 block per launch): exact first-occurrence scan ──
                int f = 0;
                while (toks[f] != t) ++f;       // terminates: toks[tid] == t
                state = (f == tid) ? 1 : 0;
            }
        }
        if (state == 1) v = __ldg(&w[t]);
    }

    // Block reduction (8 warps)
    #pragma unroll
    for (int o = 16; o > 0; o >>= 1)
        v += __shfl_down_sync(0xffffffffu, v, o);
    if ((tid & 31) == 0) warp_sums[tid >> 5] = v;
    __syncthreads();

    if (tid < 32) {
        float s = (tid < 8) ? warp_sums[tid] : 0.0f;
        #pragma unroll
        for (int o = 4; o > 0; o >>= 1)
            s += __shfl_down_sync(0xffffffffu, s, o);
        if (tid == 0) out[b] = s + bias[0];
    }
}

extern "C" void kernel_launch(void* const* d_in, const int* in_sizes, int n_in,
                              void* d_out, int out_size)
{
    const int*   text = (const int*)d_in[0];
    const float* w    = (const float*)d_in[1];
    const float* bias = (const float*)d_in[2];
    float*       out  = (float*)d_out;

    MNB_24111946400019_kernel<<<BATCH, 256>>>(text, w, bias, out);
}